// round 5
// baseline (speedup 1.0000x reference)
#include <cuda_runtime.h>

// Problem constants
#define BB    16384
#define DSUP  1024
#define DANOM 128
#define DIND  2048
#define H1D   256
#define FEAT  128
#define DEPTH 12
#define NCOND 14
#define CAP   256

// Scratch: h1 stored TRANSPOSED [256][16384] so the fused kernel reads
// contiguous rows; M_k = ref_k^T @ obj_k precomputed per bank.
__device__ float g_h1T[H1D * BB];             // 16.8 MB
__device__ float g_M[NCOND * FEAT * FEAT];    // 0.92 MB

// 8x8 register-tile FMA step: both operands read as contiguous float4 rows.
__device__ __forceinline__ void fma8x8(float acc[8][8], const float* a, const float* b)
{
    float4 a0 = *(const float4*)&a[0];
    float4 a1 = *(const float4*)&a[4];
    float4 b0 = *(const float4*)&b[0];
    float4 b1 = *(const float4*)&b[4];
    float av[8] = {a0.x,a0.y,a0.z,a0.w,a1.x,a1.y,a1.z,a1.w};
    float bv[8] = {b0.x,b0.y,b0.z,b0.w,b1.x,b1.y,b1.z,b1.w};
#pragma unroll
    for (int i = 0; i < 8; i++)
#pragma unroll
        for (int j = 0; j < 8; j++)
            acc[i][j] += av[i] * bv[j];
}

__device__ __forceinline__ void zero8x8(float acc[8][8])
{
#pragma unroll
    for (int i = 0; i < 8; i++)
#pragma unroll
        for (int j = 0; j < 8; j++)
            acc[i][j] = 0.f;
}

// ---------------------------------------------------------------------------
// Kernel A: h1 = relu([sup|anom|ind] @ W1 + b1), written transposed to g_h1T.
// SGEMM 16384x256 (K=3200). CTA tile 128x128, 256 threads, 8x8 per thread.
// Grid (128, 2), 2 CTAs/SM resident.
// ---------------------------------------------------------------------------
__global__ __launch_bounds__(256, 2)
void k_gemm1(const float* __restrict__ sup, const float* __restrict__ anom,
             const float* __restrict__ ind, const float* __restrict__ W1,
             const float* __restrict__ b1)
{
    __shared__ float As[16 * 128];   // As[kk][r]  (A transposed in smem)
    __shared__ float Bs[16 * 128];   // Bs[kk][n]
    const int tid = threadIdx.x;
    const int m0  = blockIdx.x * 128;
    const int n0  = blockIdx.y * 128;
    const int t8  = (tid >> 4) * 8;  // row sub-block (m)
    const int x8  = (tid & 15) * 8;  // col sub-block (n)

    const int ar = tid >> 2;         // A-load row
    const int aq = tid & 3;          // A-load float4 index along k
    const int bk = tid >> 5;         // B-load k row
    const int bq = tid & 31;         // B-load float4 index along n

    float acc[8][8];
    zero8x8(acc);

    const float* segP[3] = { sup, anom, ind };
    const int    segW[3] = { DSUP, DANOM, DIND };

    int kg = 0;
    for (int s = 0; s < 3; s++) {
        const float* P = segP[s];
        const int W = segW[s];
        for (int kl = 0; kl < W; kl += 16, kg += 16) {
            // load A tile with transpose (coalesced gmem float4 along k)
#pragma unroll
            for (int rep = 0; rep < 2; rep++) {
                int r = ar + rep * 64;
                float4 v = *(const float4*)&P[(m0 + r) * W + kl + aq * 4];
                As[(aq*4 + 0)*128 + r] = v.x;
                As[(aq*4 + 1)*128 + r] = v.y;
                As[(aq*4 + 2)*128 + r] = v.z;
                As[(aq*4 + 3)*128 + r] = v.w;
            }
            // load B tile (row-major copy)
#pragma unroll
            for (int rep = 0; rep < 2; rep++) {
                int kk = bk + rep * 8;
                *(float4*)&Bs[kk*128 + bq*4] =
                    *(const float4*)&W1[(kg + kk) * 256 + n0 + bq * 4];
            }
            __syncthreads();
#pragma unroll
            for (int kk = 0; kk < 16; kk++)
                fma8x8(acc, &As[kk*128 + t8], &Bs[kk*128 + x8]);
            __syncthreads();
        }
    }

    // epilogue: bias + relu, store transposed into g_h1T[n][m]
#pragma unroll
    for (int j = 0; j < 8; j++) {
        int n = n0 + x8 + j;
        float bv = b1[n];
        float v[8];
#pragma unroll
        for (int i = 0; i < 8; i++) v[i] = fmaxf(acc[i][j] + bv, 0.f);
        *(float4*)&g_h1T[n * BB + m0 + t8]     = make_float4(v[0], v[1], v[2], v[3]);
        *(float4*)&g_h1T[n * BB + m0 + t8 + 4] = make_float4(v[4], v[5], v[6], v[7]);
    }
}

// ---------------------------------------------------------------------------
// Kernel B: M_k[d][e] = sum_c ref[k][c][d] * obj[k][c][e].  Grid (14, 4),
// each CTA computes a 128x32 slab of one bank (4x4 per thread, C tiled by 64).
// ---------------------------------------------------------------------------
__global__ __launch_bounds__(256, 2)
void k_prep(const float* __restrict__ refp, const float* __restrict__ objp)
{
    __shared__ float refS[64 * 128];
    __shared__ float objS[64 * 32];
    const int k   = blockIdx.x;
    const int e0  = blockIdx.y * 32;
    const int tid = threadIdx.x;
    const int d0  = (tid >> 3) * 4;   // 0..124
    const int el  = (tid & 7) * 4;    // 0..28

    float acc[4][4];
#pragma unroll
    for (int u = 0; u < 4; u++)
#pragma unroll
        for (int v = 0; v < 4; v++) acc[u][v] = 0.f;

    for (int c0 = 0; c0 < CAP; c0 += 64) {
#pragma unroll
        for (int t = 0; t < 8; t++) {
            int idx = tid + 256 * t;
            int cc = idx >> 5, q = idx & 31;
            *(float4*)&refS[cc*128 + q*4] =
                *(const float4*)&refp[k*CAP*FEAT + (c0 + cc)*FEAT + q*4];
        }
#pragma unroll
        for (int t = 0; t < 2; t++) {
            int idx = tid + 256 * t;
            int cc = idx >> 3, q = idx & 7;
            *(float4*)&objS[cc*32 + q*4] =
                *(const float4*)&objp[k*CAP*FEAT + (c0 + cc)*FEAT + e0 + q*4];
        }
        __syncthreads();
#pragma unroll 8
        for (int cc = 0; cc < 64; cc++) {
            float4 rv = *(const float4*)&refS[cc*128 + d0];
            float4 ov = *(const float4*)&objS[cc*32 + el];
            float r[4] = {rv.x, rv.y, rv.z, rv.w};
            float o[4] = {ov.x, ov.y, ov.z, ov.w};
#pragma unroll
            for (int u = 0; u < 4; u++)
#pragma unroll
                for (int v = 0; v < 4; v++) acc[u][v] += r[u] * o[v];
        }
        __syncthreads();
    }
#pragma unroll
    for (int u = 0; u < 4; u++)
        *(float4*)&g_M[k*16384 + (d0 + u)*128 + e0 + el] =
            make_float4(acc[u][0], acc[u][1], acc[u][2], acc[u][3]);
}

// ---------------------------------------------------------------------------
// Kernel C: fused per-row pipeline, 128 rows per CTA (grid 128, 256 threads).
// State kept TRANSPOSED in smem: S_T[feat][row] -> every GEMM reads both
// operands as contiguous float4 rows (zero LDS bank conflicts).
//   GEMM2:  S_T[e][r]  = relu( sum_k W2[k][e] * h1T[k][r] + b2[e] )
//   layer:  S'_T[e][r] = relu( sum_d W[d][e]  * S_T[d][r] + b[e] )
//   bank P: P_T[e][r]  = sum_d M_k[d][e] * S_T[d][r];  iw[r] = sum_e P_T*S_T
//   bank R: R[r][e]    = sum_d S_T[d][r] * retW[d][e]  (swapped orientation
//           so output stores go straight to gmem)
//   out[r,k,e] = (R + ret_b) * (iw*IWF + aw*AWF)
// ---------------------------------------------------------------------------
#define SMEM_C_BYTES ((3 * 16384 + 256) * 4)

__global__ __launch_bounds__(256, 1)
void k_fused(const float* __restrict__ anom,
             const float* __restrict__ W2,  const float* __restrict__ b2,
             const float* __restrict__ cW,  const float* __restrict__ cB,
             const float* __restrict__ rW,  const float* __restrict__ rB,
             float* __restrict__ out)
{
    extern __shared__ float sm[];
    float* bufA = sm;                 // 16384 floats
    float* bufB = sm + 16384;         // 16384
    float* sW   = sm + 32768;         // 16384 (weight staging)
    float* aw_s = sm + 49152;         // 128
    float* iw_s = sm + 49152 + 128;   // 128

    const int tid = threadIdx.x;
    const int m0  = blockIdx.x * 128;
    const int t8  = (tid >> 4) * 8;
    const int x8  = (tid & 15) * 8;

    if (tid < 128) { aw_s[tid] = 0.f; iw_s[tid] = 0.f; }
    __syncthreads();

    // anomaly weights: aw_s[r] = sum_c |anom[m0+r][c]|   (coalesced float4)
    {
        const float4* ap = (const float4*)(anom + m0 * DANOM);
#pragma unroll
        for (int t = 0; t < 16; t++) {
            int idx = tid + 256 * t;            // float4 index; row = idx/32
            float4 v = ap[idx];
            atomicAdd(&aw_s[idx >> 5],
                      fabsf(v.x) + fabsf(v.y) + fabsf(v.z) + fabsf(v.w));
        }
    }

    float acc[8][8];
    zero8x8(acc);

    // ---- GEMM2: K = 256, tiles of 32 ----
    for (int k0 = 0; k0 < H1D; k0 += 32) {
#pragma unroll
        for (int t = 0; t < 4; t++) {
            int idx = tid + 256 * t;
            int kk = idx >> 5, q = (idx & 31) * 4;
            *(float4*)&sW[kk*128 + q]   = *(const float4*)&W2[(k0 + kk)*FEAT + q];
            *(float4*)&bufB[kk*128 + q] = *(const float4*)&g_h1T[(k0 + kk)*BB + m0 + q];
        }
        __syncthreads();
#pragma unroll 8
        for (int kk = 0; kk < 32; kk++)
            fma8x8(acc, &sW[kk*128 + t8], &bufB[kk*128 + x8]);
        __syncthreads();
    }
#pragma unroll
    for (int i = 0; i < 8; i++) {
        float bv = b2[t8 + i];
        float v[8];
#pragma unroll
        for (int j = 0; j < 8; j++) v[j] = fmaxf(acc[i][j] + bv, 0.f);
        *(float4*)&bufA[(t8 + i)*128 + x8]     = make_float4(v[0], v[1], v[2], v[3]);
        *(float4*)&bufA[(t8 + i)*128 + x8 + 4] = make_float4(v[4], v[5], v[6], v[7]);
    }
    __syncthreads();

    // ---- 12 consolidator layers ----
    float* cur = bufA;
    float* nxt = bufB;
    for (int l = 0; l < DEPTH; l++) {
        const float* w = cW + l * 16384;
#pragma unroll
        for (int t = 0; t < 16; t++) {
            int idx = (tid + 256 * t) * 4;
            *(float4*)&sW[idx] = *(const float4*)&w[idx];
        }
        __syncthreads();
        zero8x8(acc);
        {
            const float* pa = sW + t8;
            const float* pb = cur + x8;
#pragma unroll 8
            for (int d = 0; d < FEAT; d++) {
                fma8x8(acc, pa, pb);
                pa += 128; pb += 128;
            }
        }
#pragma unroll
        for (int i = 0; i < 8; i++) {
            float bv = cB[l * FEAT + t8 + i];
            float v[8];
#pragma unroll
            for (int j = 0; j < 8; j++) v[j] = fmaxf(acc[i][j] + bv, 0.f);
            *(float4*)&nxt[(t8 + i)*128 + x8]     = make_float4(v[0], v[1], v[2], v[3]);
            *(float4*)&nxt[(t8 + i)*128 + x8 + 4] = make_float4(v[4], v[5], v[6], v[7]);
        }
        __syncthreads();
        float* tmp = cur; cur = nxt; nxt = tmp;
    }

    // ---- 14 memory banks ----
    const float IWF = 0.42f * 1.8f / 256.f;   // interference scale / CAP
    const float AWF = 0.3f / 128.f;           // anomaly weight scale / D_ANOM

    for (int k = 0; k < NCOND; k++) {
        // stage M_k
        {
            const float* w = g_M + k * 16384;
#pragma unroll
            for (int t = 0; t < 16; t++) {
                int idx = (tid + 256 * t) * 4;
                *(float4*)&sW[idx] = *(const float4*)&w[idx];
            }
        }
        __syncthreads();

        // P_T[e][r] = sum_d M_k[d][e] * S_T[d][r]
        zero8x8(acc);
        {
            const float* pa = sW + t8;
            const float* pb = cur + x8;
#pragma unroll 8
            for (int d = 0; d < FEAT; d++) {
                fma8x8(acc, pa, pb);
                pa += 128; pb += 128;
            }
        }
        // iw partials: s[j] += P_T[e][r] * S_T[e][r]
        {
            float s[8];
#pragma unroll
            for (int j = 0; j < 8; j++) s[j] = 0.f;
#pragma unroll
            for (int i = 0; i < 8; i++) {
                float4 v0 = *(const float4*)&cur[(t8 + i)*128 + x8];
                float4 v1 = *(const float4*)&cur[(t8 + i)*128 + x8 + 4];
                s[0] += acc[i][0]*v0.x; s[1] += acc[i][1]*v0.y;
                s[2] += acc[i][2]*v0.z; s[3] += acc[i][3]*v0.w;
                s[4] += acc[i][4]*v1.x; s[5] += acc[i][5]*v1.y;
                s[6] += acc[i][6]*v1.z; s[7] += acc[i][7]*v1.w;
            }
#pragma unroll
            for (int j = 0; j < 8; j++) atomicAdd(&iw_s[x8 + j], s[j]);
        }
        __syncthreads();

        // stage ret_W[k]
        {
            const float* w = rW + k * 16384;
#pragma unroll
            for (int t = 0; t < 16; t++) {
                int idx = (tid + 256 * t) * 4;
                *(float4*)&sW[idx] = *(const float4*)&w[idx];
            }
        }
        __syncthreads();

        // R[r][e] = sum_d S_T[d][r] * retW[d][e]   (swapped orientation)
        zero8x8(acc);
        {
            const float* pa = cur + t8;   // r rows
            const float* pb = sW + x8;    // e cols
#pragma unroll 8
            for (int d = 0; d < FEAT; d++) {
                fma8x8(acc, pa, pb);
                pa += 128; pb += 128;
            }
        }

        // epilogue: apply combined weight, store directly to gmem
        float4 rb0 = *(const float4*)&rB[k * FEAT + x8];
        float4 rb1 = *(const float4*)&rB[k * FEAT + x8 + 4];
#pragma unroll
        for (int i = 0; i < 8; i++) {
            int r = t8 + i;
            float wgt = iw_s[r] * IWF + aw_s[r] * AWF;
            float* op = out + ((m0 + r) * NCOND + k) * FEAT + x8;
            *(float4*)&op[0] = make_float4((acc[i][0] + rb0.x) * wgt,
                                           (acc[i][1] + rb0.y) * wgt,
                                           (acc[i][2] + rb0.z) * wgt,
                                           (acc[i][3] + rb0.w) * wgt);
            *(float4*)&op[4] = make_float4((acc[i][4] + rb1.x) * wgt,
                                           (acc[i][5] + rb1.y) * wgt,
                                           (acc[i][6] + rb1.z) * wgt,
                                           (acc[i][7] + rb1.w) * wgt);
        }
        __syncthreads();
        if (tid < 128) iw_s[tid] = 0.f;   // for next bank (before its post-load sync)
    }
}

// ---------------------------------------------------------------------------
extern "C" void kernel_launch(void* const* d_in, const int* in_sizes, int n_in,
                              void* d_out, int out_size)
{
    (void)in_sizes; (void)n_in; (void)out_size;
    const float* sup  = (const float*)d_in[0];
    const float* anom = (const float*)d_in[1];
    const float* ind  = (const float*)d_in[2];
    const float* W1   = (const float*)d_in[3];
    const float* b1   = (const float*)d_in[4];
    const float* W2   = (const float*)d_in[5];
    const float* b2   = (const float*)d_in[6];
    const float* cW   = (const float*)d_in[7];
    const float* cB   = (const float*)d_in[8];
    const float* refp = (const float*)d_in[9];
    const float* objp = (const float*)d_in[10];
    const float* rW   = (const float*)d_in[11];
    const float* rB   = (const float*)d_in[12];
    float* out = (float*)d_out;

    cudaFuncSetAttribute(k_fused, cudaFuncAttributeMaxDynamicSharedMemorySize,
                         SMEM_C_BYTES);

    k_gemm1<<<dim3(128, 2), 256>>>(sup, anom, ind, W1, b1);
    k_prep<<<dim3(NCOND, 4), 256>>>(refp, objp);
    k_fused<<<128, 256, SMEM_C_BYTES>>>(anom, W2, b2, cW, cB, rW, rB, out);
}

// round 8
// speedup vs baseline: 1.0101x; 1.0101x over previous
#include <cuda_runtime.h>

// Problem constants
#define BB    16384
#define DSUP  1024
#define DANOM 128
#define DIND  2048
#define H1D   256
#define FEAT  128
#define DEPTH 12
#define NCOND 14
#define CAP   256

typedef unsigned long long u64;

// Scratch: h1 stored TRANSPOSED [256][16384]; M_k = ref_k^T @ obj_k per bank.
__device__ float g_h1T[H1D * BB];             // 16.8 MB
__device__ float g_M[NCOND * FEAT * FEAT];    // 0.92 MB

// ---------------------------------------------------------------------------
// Packed fp32x2 primitives (sm_100+). ptxas never auto-fuses these.
// ---------------------------------------------------------------------------
__device__ __forceinline__ u64 ffma2(u64 a, u64 b, u64 c)
{
    u64 d;
    asm("fma.rn.f32x2 %0, %1, %2, %3;" : "=l"(d) : "l"(a), "l"(b), "l"(c));
    return d;
}
__device__ __forceinline__ u64 splat2(float x)
{
    u64 d;
    asm("mov.b64 %0, {%1, %1};" : "=l"(d) : "f"(x));
    return d;
}
__device__ __forceinline__ float2 unpk(u64 v)
{
    float2 f;
    asm("mov.b64 {%0, %1}, %2;" : "=f"(f.x), "=f"(f.y) : "l"(v));
    return f;
}

__device__ __forceinline__ void zacc(u64 acc[8][4])
{
#pragma unroll
    for (int i = 0; i < 8; i++)
#pragma unroll
        for (int j = 0; j < 4; j++) acc[i][j] = 0ull;
}

// One k-step: acc[i][j] += splat(aS[i]) * pair(bP[2j..2j+1]).
// aS: 8 scalars (warp-broadcast smem reads). bP: 8 floats read as 4 u64 pairs.
__device__ __forceinline__ void gstep(u64 acc[8][4], const float* aS, const float* bP)
{
    float4 a0 = *(const float4*)&aS[0];
    float4 a1 = *(const float4*)&aS[4];
    float av[8] = {a0.x, a0.y, a0.z, a0.w, a1.x, a1.y, a1.z, a1.w};
    const ulonglong2* bp = (const ulonglong2*)bP;
    ulonglong2 b01 = bp[0], b23 = bp[1];
    u64 bv[4] = {b01.x, b01.y, b23.x, b23.y};
    u64 as_[8];
#pragma unroll
    for (int i = 0; i < 8; i++) as_[i] = splat2(av[i]);
#pragma unroll
    for (int i = 0; i < 8; i++)
#pragma unroll
        for (int j = 0; j < 4; j++)
            acc[i][j] = ffma2(as_[i], bv[j], acc[i][j]);
}

// ---------------------------------------------------------------------------
// Kernel A: h1 = relu([sup|anom|ind] @ W1 + b1), written transposed to g_h1T.
// CTA tile 64m x 256n (full N), grid 256, 256 threads, 2 CTAs/SM.
// Thread tile: 8 n (splatted) x 8 m (packed pairs -> contiguous h1T stores).
// ---------------------------------------------------------------------------
__global__ __launch_bounds__(256, 2)
void k_gemm1(const float* __restrict__ sup, const float* __restrict__ anom,
             const float* __restrict__ ind, const float* __restrict__ W1,
             const float* __restrict__ b1)
{
    __shared__ __align__(16) float As[16 * 64];    // [kk][m]  (A transposed), 4 KB
    __shared__ __align__(16) float Bs[16 * 256];   // [kk][n], 16 KB
    const int tid = threadIdx.x;
    const int m0  = blockIdx.x * 64;
    const int tm  = (tid >> 5) * 8;   // m sub-block (warp-uniform!)
    const int xn  = (tid & 31) * 8;   // n sub-block

    const int ar = tid >> 2;          // A-load row (0..63)
    const int ac = tid & 3;           // A-load float4 index along k

    u64 acc[8][4];                    // [n][m-pair]
    zacc(acc);

    const float* segP[3] = { sup, anom, ind };
    const int    segW[3] = { DSUP, DANOM, DIND };

    int kg = 0;
    for (int s = 0; s < 3; s++) {
        const float* P = segP[s];
        const int W = segW[s];
        for (int kl = 0; kl < W; kl += 16, kg += 16) {
            // A tile: each thread one float4 along k, transposed into As
            float4 va = *(const float4*)&P[(m0 + ar) * W + kl + ac * 4];
            As[(ac * 4 + 0) * 64 + ar] = va.x;
            As[(ac * 4 + 1) * 64 + ar] = va.y;
            As[(ac * 4 + 2) * 64 + ar] = va.z;
            As[(ac * 4 + 3) * 64 + ar] = va.w;
            // B tile: 16x256 floats = 1024 float4s
#pragma unroll
            for (int t = 0; t < 4; t++) {
                int idx = tid + 256 * t;
                int kk = idx >> 6, q = idx & 63;
                *(float4*)&Bs[kk * 256 + q * 4] =
                    *(const float4*)&W1[(kg + kk) * 256 + q * 4];
            }
            __syncthreads();
#pragma unroll
            for (int kk = 0; kk < 16; kk++)
                gstep(acc, &Bs[kk * 256 + xn], &As[kk * 64 + tm]);
            __syncthreads();
        }
    }

    // epilogue: bias + relu, store transposed into g_h1T[n][m]
#pragma unroll
    for (int j = 0; j < 8; j++) {
        int n = xn + j;
        float bv = b1[n];
        float v[8];
#pragma unroll
        for (int i = 0; i < 4; i++) {
            float2 p = unpk(acc[j][i]);
            v[2 * i]     = fmaxf(p.x + bv, 0.f);
            v[2 * i + 1] = fmaxf(p.y + bv, 0.f);
        }
        *(float4*)&g_h1T[n * BB + m0 + tm]     = make_float4(v[0], v[1], v[2], v[3]);
        *(float4*)&g_h1T[n * BB + m0 + tm + 4] = make_float4(v[4], v[5], v[6], v[7]);
    }
}

// ---------------------------------------------------------------------------
// Kernel B: M_k[d][e] = sum_c ref[k][c][d] * obj[k][c][e].  Tiny (117 MFLOP).
// ---------------------------------------------------------------------------
__global__ __launch_bounds__(256, 2)
void k_prep(const float* __restrict__ refp, const float* __restrict__ objp)
{
    __shared__ __align__(16) float refS[64 * 128];
    __shared__ __align__(16) float objS[64 * 32];
    const int k   = blockIdx.x;
    const int e0  = blockIdx.y * 32;
    const int tid = threadIdx.x;
    const int d0  = (tid >> 3) * 4;
    const int el  = (tid & 7) * 4;

    float acc[4][4];
#pragma unroll
    for (int u = 0; u < 4; u++)
#pragma unroll
        for (int v = 0; v < 4; v++) acc[u][v] = 0.f;

    for (int c0 = 0; c0 < CAP; c0 += 64) {
#pragma unroll
        for (int t = 0; t < 8; t++) {
            int idx = tid + 256 * t;
            int cc = idx >> 5, q = idx & 31;
            *(float4*)&refS[cc * 128 + q * 4] =
                *(const float4*)&refp[k * CAP * FEAT + (c0 + cc) * FEAT + q * 4];
        }
#pragma unroll
        for (int t = 0; t < 2; t++) {
            int idx = tid + 256 * t;
            int cc = idx >> 3, q = idx & 7;
            *(float4*)&objS[cc * 32 + q * 4] =
                *(const float4*)&objp[k * CAP * FEAT + (c0 + cc) * FEAT + e0 + q * 4];
        }
        __syncthreads();
#pragma unroll 8
        for (int cc = 0; cc < 64; cc++) {
            float4 rv = *(const float4*)&refS[cc * 128 + d0];
            float4 ov = *(const float4*)&objS[cc * 32 + el];
            float r[4] = {rv.x, rv.y, rv.z, rv.w};
            float o[4] = {ov.x, ov.y, ov.z, ov.w};
#pragma unroll
            for (int u = 0; u < 4; u++)
#pragma unroll
                for (int v = 0; v < 4; v++) acc[u][v] += r[u] * o[v];
        }
        __syncthreads();
    }
#pragma unroll
    for (int u = 0; u < 4; u++)
        *(float4*)&g_M[k * 16384 + (d0 + u) * 128 + e0 + el] =
            make_float4(acc[u][0], acc[u][1], acc[u][2], acc[u][3]);
}

// ---------------------------------------------------------------------------
// Kernel C: fused per-row pipeline, 128 rows per CTA (grid 128, 256 threads).
// State kept TRANSPOSED in smem: S_T[feat][row]. All GEMMs use the packed
// step: splat the t8-indexed operand (warp-broadcast), pair the x8-indexed one.
// smem: bufA(16384) + bufB(16384) + sW(16384 = FEAT*FEAT!) + aw(128) + iw(128)
// ---------------------------------------------------------------------------
#define SMEM_C_BYTES ((3 * 16384 + 256) * 4)

__global__ __launch_bounds__(256, 1)
void k_fused(const float* __restrict__ anom,
             const float* __restrict__ W2,  const float* __restrict__ b2,
             const float* __restrict__ cW,  const float* __restrict__ cB,
             const float* __restrict__ rW,  const float* __restrict__ rB,
             float* __restrict__ out)
{
    extern __shared__ float sm[];
    float* bufA = sm;                 // 16384 floats
    float* bufB = sm + 16384;         // 16384
    float* sW   = sm + 32768;         // 16384 (weight staging, 64 KB)
    float* aw_s = sm + 49152;         // 128
    float* iw_s = sm + 49152 + 128;   // 128

    const int tid = threadIdx.x;
    const int m0  = blockIdx.x * 128;
    const int t8  = (tid >> 4) * 8;
    const int x8  = (tid & 15) * 8;

    if (tid < 128) { aw_s[tid] = 0.f; iw_s[tid] = 0.f; }
    __syncthreads();

    // anomaly weights: aw_s[r] = sum_c |anom[m0+r][c]|
    {
        const float4* ap = (const float4*)(anom + m0 * DANOM);
#pragma unroll
        for (int t = 0; t < 16; t++) {
            int idx = tid + 256 * t;
            float4 v = ap[idx];
            atomicAdd(&aw_s[idx >> 5],
                      fabsf(v.x) + fabsf(v.y) + fabsf(v.z) + fabsf(v.w));
        }
    }

    u64 acc[8][4];
    zacc(acc);

    // ---- GEMM2: S_T[e][r] = relu(sum_k W2[k][e] * h1T[k][r] + b2[e]) ----
    for (int k0 = 0; k0 < H1D; k0 += 32) {
#pragma unroll
        for (int t = 0; t < 4; t++) {
            int idx = tid + 256 * t;
            int kk = idx >> 5, q = (idx & 31) * 4;
            *(float4*)&sW[kk * 128 + q]   = *(const float4*)&W2[(k0 + kk) * FEAT + q];
            *(float4*)&bufB[kk * 128 + q] = *(const float4*)&g_h1T[(k0 + kk) * BB + m0 + q];
        }
        __syncthreads();
#pragma unroll 8
        for (int kk = 0; kk < 32; kk++)
            gstep(acc, &sW[kk * 128 + t8], &bufB[kk * 128 + x8]);
        __syncthreads();
    }
#pragma unroll
    for (int i = 0; i < 8; i++) {
        float bv = b2[t8 + i];
        float v[8];
#pragma unroll
        for (int j = 0; j < 4; j++) {
            float2 p = unpk(acc[i][j]);
            v[2 * j]     = fmaxf(p.x + bv, 0.f);
            v[2 * j + 1] = fmaxf(p.y + bv, 0.f);
        }
        *(float4*)&bufA[(t8 + i) * 128 + x8]     = make_float4(v[0], v[1], v[2], v[3]);
        *(float4*)&bufA[(t8 + i) * 128 + x8 + 4] = make_float4(v[4], v[5], v[6], v[7]);
    }
    __syncthreads();

    // ---- 12 consolidator layers ----
    float* cur = bufA;
    float* nxt = bufB;
    for (int l = 0; l < DEPTH; l++) {
        const float* w = cW + l * 16384;
#pragma unroll
        for (int t = 0; t < 16; t++) {
            int idx = (tid + 256 * t) * 4;
            *(float4*)&sW[idx] = *(const float4*)&w[idx];
        }
        __syncthreads();
        zacc(acc);
        {
            const float* pa = sW + t8;
            const float* pb = cur + x8;
#pragma unroll 8
            for (int d = 0; d < FEAT; d++) {
                gstep(acc, pa, pb);
                pa += 128; pb += 128;
            }
        }
#pragma unroll
        for (int i = 0; i < 8; i++) {
            float bv = cB[l * FEAT + t8 + i];
            float v[8];
#pragma unroll
            for (int j = 0; j < 4; j++) {
                float2 p = unpk(acc[i][j]);
                v[2 * j]     = fmaxf(p.x + bv, 0.f);
                v[2 * j + 1] = fmaxf(p.y + bv, 0.f);
            }
            *(float4*)&nxt[(t8 + i) * 128 + x8]     = make_float4(v[0], v[1], v[2], v[3]);
            *(float4*)&nxt[(t8 + i) * 128 + x8 + 4] = make_float4(v[4], v[5], v[6], v[7]);
        }
        __syncthreads();
        float* tmp = cur; cur = nxt; nxt = tmp;
    }

    // ---- 14 memory banks ----
    const float IWF = 0.42f * 1.8f / 256.f;
    const float AWF = 0.3f / 128.f;

    for (int k = 0; k < NCOND; k++) {
        // stage M_k
        {
            const float* w = g_M + k * 16384;
#pragma unroll
            for (int t = 0; t < 16; t++) {
                int idx = (tid + 256 * t) * 4;
                *(float4*)&sW[idx] = *(const float4*)&w[idx];
            }
        }
        __syncthreads();

        // P_T[e][r] = sum_d M_k[d][e] * S_T[d][r]   (acc[e][r-pairs])
        zacc(acc);
        {
            const float* pa = sW + t8;
            const float* pb = cur + x8;
#pragma unroll 8
            for (int d = 0; d < FEAT; d++) {
                gstep(acc, pa, pb);
                pa += 128; pb += 128;
            }
        }
        // iw partials: s[j] += P_T[e][r] * S_T[e][r]
        {
            float s[8];
#pragma unroll
            for (int j = 0; j < 8; j++) s[j] = 0.f;
#pragma unroll
            for (int i = 0; i < 8; i++) {
                float4 v0 = *(const float4*)&cur[(t8 + i) * 128 + x8];
                float4 v1 = *(const float4*)&cur[(t8 + i) * 128 + x8 + 4];
                float2 p;
                p = unpk(acc[i][0]); s[0] += p.x * v0.x; s[1] += p.y * v0.y;
                p = unpk(acc[i][1]); s[2] += p.x * v0.z; s[3] += p.y * v0.w;
                p = unpk(acc[i][2]); s[4] += p.x * v1.x; s[5] += p.y * v1.y;
                p = unpk(acc[i][3]); s[6] += p.x * v1.z; s[7] += p.y * v1.w;
            }
#pragma unroll
            for (int j = 0; j < 8; j++) atomicAdd(&iw_s[x8 + j], s[j]);
        }
        __syncthreads();

        // stage ret_W[k]
        {
            const float* w = rW + k * 16384;
#pragma unroll
            for (int t = 0; t < 16; t++) {
                int idx = (tid + 256 * t) * 4;
                *(float4*)&sW[idx] = *(const float4*)&w[idx];
            }
        }
        __syncthreads();

        // R[r][e] = sum_d S_T[d][r] * retW[d][e]   (acc[r][e-pairs])
        zacc(acc);
        {
            const float* pa = cur + t8;   // splat state rows (warp-broadcast)
            const float* pb = sW + x8;    // pair retW cols
#pragma unroll 8
            for (int d = 0; d < FEAT; d++) {
                gstep(acc, pa, pb);
                pa += 128; pb += 128;
            }
        }

        // epilogue: apply combined weight, store directly to gmem
        float4 rb0 = *(const float4*)&rB[k * FEAT + x8];
        float4 rb1 = *(const float4*)&rB[k * FEAT + x8 + 4];
        float rbv[8] = {rb0.x, rb0.y, rb0.z, rb0.w, rb1.x, rb1.y, rb1.z, rb1.w};
#pragma unroll
        for (int i = 0; i < 8; i++) {
            int r = t8 + i;
            float wgt = iw_s[r] * IWF + aw_s[r] * AWF;
            float v[8];
#pragma unroll
            for (int j = 0; j < 4; j++) {
                float2 p = unpk(acc[i][j]);
                v[2 * j]     = (p.x + rbv[2 * j]) * wgt;
                v[2 * j + 1] = (p.y + rbv[2 * j + 1]) * wgt;
            }
            float* op = out + ((m0 + r) * NCOND + k) * FEAT + x8;
            *(float4*)&op[0] = make_float4(v[0], v[1], v[2], v[3]);
            *(float4*)&op[4] = make_float4(v[4], v[5], v[6], v[7]);
        }
        __syncthreads();
        if (tid < 128) iw_s[tid] = 0.f;   // reset for next bank
    }
}

// ---------------------------------------------------------------------------
extern "C" void kernel_launch(void* const* d_in, const int* in_sizes, int n_in,
                              void* d_out, int out_size)
{
    (void)in_sizes; (void)n_in; (void)out_size;
    const float* sup  = (const float*)d_in[0];
    const float* anom = (const float*)d_in[1];
    const float* ind  = (const float*)d_in[2];
    const float* W1   = (const float*)d_in[3];
    const float* b1   = (const float*)d_in[4];
    const float* W2   = (const float*)d_in[5];
    const float* b2   = (const float*)d_in[6];
    const float* cW   = (const float*)d_in[7];
    const float* cB   = (const float*)d_in[8];
    const float* refp = (const float*)d_in[9];
    const float* objp = (const float*)d_in[10];
    const float* rW   = (const float*)d_in[11];
    const float* rB   = (const float*)d_in[12];
    float* out = (float*)d_out;

    cudaFuncSetAttribute(k_fused, cudaFuncAttributeMaxDynamicSharedMemorySize,
                         SMEM_C_BYTES);

    k_gemm1<<<256, 256>>>(sup, anom, ind, W1, b1);
    k_prep<<<dim3(NCOND, 4), 256>>>(refp, objp);
    k_fused<<<128, 256, SMEM_C_BYTES>>>(anom, W2, b2, cW, cB, rW, rB, out);
}

// round 15
// speedup vs baseline: 1.5185x; 1.5032x over previous
#include <cuda_runtime.h>
#include <cuda_bf16.h>
#include <cstdint>

// Problem constants
#define BB    16384
#define DSUP  1024
#define DANOM 128
#define DIND  2048
#define DIN   3200
#define H1D   256
#define FEAT  128
#define DEPTH 12
#define NCOND 14
#define CAP   256

typedef unsigned long long u64;

// Scratch
__device__ float g_h1T[H1D * BB];                  // 16.8 MB, h1 transposed [256][16384]
__device__ float g_M[NCOND * FEAT * FEAT];         // 0.92 MB
__device__ __nv_bfloat16 g_Bhi[H1D * DIN];         // W1^T hi  [256][3200]
__device__ __nv_bfloat16 g_Blo[H1D * DIN];         // W1^T lo

__device__ __forceinline__ uint32_t smem_u32(const void* p) {
    uint32_t a;
    asm("{ .reg .u64 t; cvta.to.shared.u64 t, %1; cvt.u32.u64 %0, t; }"
        : "=r"(a) : "l"(p));
    return a;
}

// ---------------------------------------------------------------------------
// mma.sync / ldmatrix macros (sm_80-level -> valid on sm_103 family target)
// ---------------------------------------------------------------------------
#define LDMX4(r0, r1, r2, r3, addr) \
    asm volatile("ldmatrix.sync.aligned.m8n8.x4.shared.b16 {%0,%1,%2,%3}, [%4];" \
        : "=r"(r0), "=r"(r1), "=r"(r2), "=r"(r3) : "r"(addr))
#define LDMX2(r0, r1, addr) \
    asm volatile("ldmatrix.sync.aligned.m8n8.x2.shared.b16 {%0,%1}, [%2];" \
        : "=r"(r0), "=r"(r1) : "r"(addr))
#define MMA16816(d, a, b0_, b1_) \
    asm volatile("mma.sync.aligned.m16n8k16.row.col.f32.bf16.bf16.f32 " \
        "{%0,%1,%2,%3}, {%4,%5,%6,%7}, {%8,%9}, {%0,%1,%2,%3};" \
        : "+f"((d)[0]), "+f"((d)[1]), "+f"((d)[2]), "+f"((d)[3]) \
        : "r"((a)[0]), "r"((a)[1]), "r"((a)[2]), "r"((a)[3]), \
          "r"(b0_), "r"(b1_))

// ---------------------------------------------------------------------------
// k_prepB: transpose + split W1 [3200][256] fp32 -> g_Bhi/g_Blo [256][3200] bf16
// ---------------------------------------------------------------------------
__global__ __launch_bounds__(256)
void k_prepB(const float* __restrict__ W1)
{
    __shared__ float t[32][33];
    const int k0 = blockIdx.x * 32;   // 100
    const int n0 = blockIdx.y * 32;   // 8
    const int tx = threadIdx.x & 31, ty = threadIdx.x >> 5;  // ty 0..7
#pragma unroll
    for (int i = 0; i < 32; i += 8)
        t[ty + i][tx] = W1[(k0 + ty + i) * H1D + n0 + tx];
    __syncthreads();
#pragma unroll
    for (int i = 0; i < 32; i += 8) {
        int n = n0 + ty + i, k = k0 + tx;
        float x = t[tx][ty + i];
        __nv_bfloat16 hi = __float2bfloat16(x);
        __nv_bfloat16 lo = __float2bfloat16(x - __bfloat162float(hi));
        g_Bhi[n * DIN + k] = hi;
        g_Blo[n * DIN + k] = lo;
    }
}

// ---------------------------------------------------------------------------
// k_gemm1_mma: h1 = relu(X @ W1 + b1) via split-bf16 mma.sync m16n8k16.
// CTA 128m x 256n, grid 128, 256 threads (8 warps = 2m x 4n, warp tile 64x64).
// K chunks of 64; double-buffered smem; A fp32->hi/lo converted in-kernel,
// B pre-split by k_prepB. Smem rows padded to 144 B (conflict-free ldmatrix).
// ---------------------------------------------------------------------------
#define KCH 64
#define NCH (DIN / KCH)      // 50
#define A_HI 0
#define A_LO 18432           // 128 * 144
#define B_HI 36864
#define B_LO (36864 + 36864) // 256 * 144 after B_HI
#define BUFB 110592          // A(2x18432) + B(2x36864)
#define SMEM_G1B (2 * BUFB)  // 221184

__device__ __forceinline__ void g1_loadA(float4* areg, int c, int m0, int tid,
    const float* __restrict__ sup, const float* __restrict__ anom,
    const float* __restrict__ ind)
{
    const int kg = c * KCH;
    const float* P; int W, koff;
    if (kg < DSUP)              { P = sup;  W = DSUP;  koff = kg; }
    else if (kg < DSUP + DANOM) { P = anom; W = DANOM; koff = kg - DSUP; }
    else                        { P = ind;  W = DIND;  koff = kg - DSUP - DANOM; }
#pragma unroll
    for (int it = 0; it < 8; it++) {
        int idx = tid + 256 * it;
        int r = idx >> 4, q = idx & 15;
        areg[it] = *(const float4*)&P[(m0 + r) * W + koff + q * 4];
    }
}

__device__ __forceinline__ void g1_store(const float4* areg, int c, int tid, char* ab)
{
#pragma unroll
    for (int it = 0; it < 8; it++) {
        int idx = tid + 256 * it;
        int r = idx >> 4, q = idx & 15;
        float4 v = areg[it];
        float xs[4] = {v.x, v.y, v.z, v.w};
        unsigned short hs[4], ls[4];
#pragma unroll
        for (int j = 0; j < 4; j++) {
            __nv_bfloat16 h = __float2bfloat16(xs[j]);
            __nv_bfloat16 l = __float2bfloat16(xs[j] - __bfloat162float(h));
            hs[j] = __bfloat16_as_ushort(h);
            ls[j] = __bfloat16_as_ushort(l);
        }
        uint2 hv = make_uint2((uint32_t)hs[0] | ((uint32_t)hs[1] << 16),
                              (uint32_t)hs[2] | ((uint32_t)hs[3] << 16));
        uint2 lv = make_uint2((uint32_t)ls[0] | ((uint32_t)ls[1] << 16),
                              (uint32_t)ls[2] | ((uint32_t)ls[3] << 16));
        *(uint2*)(ab + A_HI + r * 144 + q * 8) = hv;
        *(uint2*)(ab + A_LO + r * 144 + q * 8) = lv;
    }
    const int kg = c * KCH;
#pragma unroll
    for (int it = 0; it < 8; it++) {
        int idx = tid + 256 * it;
        int n = idx >> 3, u = idx & 7;
        *(uint4*)(ab + B_HI + n * 144 + u * 16) =
            *(const uint4*)&g_Bhi[n * DIN + kg + u * 8];
    }
#pragma unroll
    for (int it = 0; it < 8; it++) {
        int idx = tid + 256 * it;
        int n = idx >> 3, u = idx & 7;
        *(uint4*)(ab + B_LO + n * 144 + u * 16) =
            *(const uint4*)&g_Blo[n * DIN + kg + u * 8];
    }
}

__global__ __launch_bounds__(256)
void k_gemm1_mma(const float* __restrict__ sup, const float* __restrict__ anom,
                 const float* __restrict__ ind, const float* __restrict__ b1)
{
    extern __shared__ __align__(16) char smem[];
    const uint32_t sbase = smem_u32(smem);
    const int tid  = threadIdx.x;
    const int lane = tid & 31;
    const int wid  = tid >> 5;
    const int wm   = wid >> 2;   // 0..1
    const int wn   = wid & 3;    // 0..3
    const int m0   = blockIdx.x * 128;

    float acc[4][8][4];
#pragma unroll
    for (int i = 0; i < 4; i++)
#pragma unroll
        for (int j = 0; j < 8; j++)
#pragma unroll
            for (int r = 0; r < 4; r++) acc[i][j][r] = 0.f;

    float4 areg[8];
    g1_loadA(areg, 0, m0, tid, sup, anom, ind);
    g1_store(areg, 0, tid, smem);
    __syncthreads();

    for (int c = 0; c < NCH; c++) {
        const int b = c & 1;
        if (c + 1 < NCH)
            g1_loadA(areg, c + 1, m0, tid, sup, anom, ind);   // prefetch to regs

        const uint32_t base = sbase + b * BUFB;
        const uint32_t arow0 = base + A_HI + (wm * 64 + (lane & 15)) * 144
                               + (lane >> 4) * 16;
        const uint32_t brow0 = base + B_HI + (wn * 64 + (lane & 7)) * 144
                               + ((lane >> 3) & 1) * 16;
#pragma unroll
        for (int ks = 0; ks < 4; ks++) {
            uint32_t ah[4][4], al[4][4];
#pragma unroll
            for (int i = 0; i < 4; i++) {
                uint32_t aa = arow0 + i * (16 * 144) + ks * 32;
                LDMX4(ah[i][0], ah[i][1], ah[i][2], ah[i][3], aa);
                LDMX4(al[i][0], al[i][1], al[i][2], al[i][3], aa + (A_LO - A_HI));
            }
#pragma unroll
            for (int j = 0; j < 8; j++) {
                uint32_t bh0, bh1, bl0, bl1;
                uint32_t ba = brow0 + j * (8 * 144) + ks * 32;
                LDMX2(bh0, bh1, ba);
                LDMX2(bl0, bl1, ba + (B_LO - B_HI));
#pragma unroll
                for (int i = 0; i < 4; i++) {
                    MMA16816(acc[i][j], ah[i], bh0, bh1);
                    MMA16816(acc[i][j], ah[i], bl0, bl1);
                    MMA16816(acc[i][j], al[i], bh0, bh1);
                }
            }
        }
        if (c + 1 < NCH)
            g1_store(areg, c + 1, tid, smem + ((c + 1) & 1) * BUFB);
        __syncthreads();
    }

    // epilogue: bias + relu, store h1T[n][m]
    const int q    = lane & 3;
    const int rrow = lane >> 2;
#pragma unroll
    for (int i = 0; i < 4; i++) {
        int m = m0 + wm * 64 + i * 16 + rrow;
#pragma unroll
        for (int j = 0; j < 8; j++) {
            int nb = wn * 64 + j * 8 + 2 * q;
            float b0v = b1[nb], b1v = b1[nb + 1];
            g_h1T[nb * BB + m]           = fmaxf(acc[i][j][0] + b0v, 0.f);
            g_h1T[(nb + 1) * BB + m]     = fmaxf(acc[i][j][1] + b1v, 0.f);
            g_h1T[nb * BB + m + 8]       = fmaxf(acc[i][j][2] + b0v, 0.f);
            g_h1T[(nb + 1) * BB + m + 8] = fmaxf(acc[i][j][3] + b1v, 0.f);
        }
    }
}

// ---------------------------------------------------------------------------
// Kernel B: M_k[d][e] = sum_c ref[k][c][d] * obj[k][c][e].
// ---------------------------------------------------------------------------
__global__ __launch_bounds__(256, 2)
void k_prep(const float* __restrict__ refp, const float* __restrict__ objp)
{
    __shared__ __align__(16) float refS[64 * 128];
    __shared__ __align__(16) float objS[64 * 32];
    const int k   = blockIdx.x;
    const int e0  = blockIdx.y * 32;
    const int tid = threadIdx.x;
    const int d0  = (tid >> 3) * 4;
    const int el  = (tid & 7) * 4;

    float acc[4][4];
#pragma unroll
    for (int u = 0; u < 4; u++)
#pragma unroll
        for (int v = 0; v < 4; v++) acc[u][v] = 0.f;

    for (int c0 = 0; c0 < CAP; c0 += 64) {
#pragma unroll
        for (int t = 0; t < 8; t++) {
            int idx = tid + 256 * t;
            int cc = idx >> 5, qq = idx & 31;
            *(float4*)&refS[cc * 128 + qq * 4] =
                *(const float4*)&refp[k * CAP * FEAT + (c0 + cc) * FEAT + qq * 4];
        }
#pragma unroll
        for (int t = 0; t < 2; t++) {
            int idx = tid + 256 * t;
            int cc = idx >> 3, qq = idx & 7;
            *(float4*)&objS[cc * 32 + qq * 4] =
                *(const float4*)&objp[k * CAP * FEAT + (c0 + cc) * FEAT + e0 + qq * 4];
        }
        __syncthreads();
#pragma unroll 8
        for (int cc = 0; cc < 64; cc++) {
            float4 rv = *(const float4*)&refS[cc * 128 + d0];
            float4 ov = *(const float4*)&objS[cc * 32 + el];
            float r[4] = {rv.x, rv.y, rv.z, rv.w};
            float o[4] = {ov.x, ov.y, ov.z, ov.w};
#pragma unroll
            for (int u = 0; u < 4; u++)
#pragma unroll
                for (int v = 0; v < 4; v++) acc[u][v] += r[u] * o[v];
        }
        __syncthreads();
    }
#pragma unroll
    for (int u = 0; u < 4; u++)
        *(float4*)&g_M[k * 16384 + (d0 + u) * 128 + e0 + el] =
            make_float4(acc[u][0], acc[u][1], acc[u][2], acc[u][3]);
}

// ---------------------------------------------------------------------------
// fp32x2 packed helpers for k_fused (unchanged from passing R8 build)
// ---------------------------------------------------------------------------
__device__ __forceinline__ u64 ffma2(u64 a, u64 b, u64 c)
{
    u64 d;
    asm("fma.rn.f32x2 %0, %1, %2, %3;" : "=l"(d) : "l"(a), "l"(b), "l"(c));
    return d;
}
__device__ __forceinline__ u64 splat2(float x)
{
    u64 d;
    asm("mov.b64 %0, {%1, %1};" : "=l"(d) : "f"(x));
    return d;
}
__device__ __forceinline__ float2 unpk(u64 v)
{
    float2 f;
    asm("mov.b64 {%0, %1}, %2;" : "=f"(f.x), "=f"(f.y) : "l"(v));
    return f;
}
__device__ __forceinline__ void zacc(u64 acc[8][4])
{
#pragma unroll
    for (int i = 0; i < 8; i++)
#pragma unroll
        for (int j = 0; j < 4; j++) acc[i][j] = 0ull;
}
__device__ __forceinline__ void gstep(u64 acc[8][4], const float* aS, const float* bP)
{
    float4 a0 = *(const float4*)&aS[0];
    float4 a1 = *(const float4*)&aS[4];
    float av[8] = {a0.x, a0.y, a0.z, a0.w, a1.x, a1.y, a1.z, a1.w};
    const ulonglong2* bp = (const ulonglong2*)bP;
    ulonglong2 b01 = bp[0], b23 = bp[1];
    u64 bv[4] = {b01.x, b01.y, b23.x, b23.y};
    u64 as_[8];
#pragma unroll
    for (int i = 0; i < 8; i++) as_[i] = splat2(av[i]);
#pragma unroll
    for (int i = 0; i < 8; i++)
#pragma unroll
        for (int j = 0; j < 4; j++)
            acc[i][j] = ffma2(as_[i], bv[j], acc[i][j]);
}

// ---------------------------------------------------------------------------
// Kernel C: fused per-row pipeline (unchanged from passing R8 build).
// ---------------------------------------------------------------------------
#define SMEM_C_BYTES ((3 * 16384 + 256) * 4)

__global__ __launch_bounds__(256, 1)
void k_fused(const float* __restrict__ anom,
             const float* __restrict__ W2,  const float* __restrict__ b2,
             const float* __restrict__ cW,  const float* __restrict__ cB,
             const float* __restrict__ rW,  const float* __restrict__ rB,
             float* __restrict__ out)
{
    extern __shared__ float sm[];
    float* bufA = sm;
    float* bufB = sm + 16384;
    float* sW   = sm + 32768;
    float* aw_s = sm + 49152;
    float* iw_s = sm + 49152 + 128;

    const int tid = threadIdx.x;
    const int m0  = blockIdx.x * 128;
    const int t8  = (tid >> 4) * 8;
    const int x8  = (tid & 15) * 8;

    if (tid < 128) { aw_s[tid] = 0.f; iw_s[tid] = 0.f; }
    __syncthreads();

    {
        const float4* ap = (const float4*)(anom + m0 * DANOM);
#pragma unroll
        for (int t = 0; t < 16; t++) {
            int idx = tid + 256 * t;
            float4 v = ap[idx];
            atomicAdd(&aw_s[idx >> 5],
                      fabsf(v.x) + fabsf(v.y) + fabsf(v.z) + fabsf(v.w));
        }
    }

    u64 acc[8][4];
    zacc(acc);

    for (int k0 = 0; k0 < H1D; k0 += 32) {
#pragma unroll
        for (int t = 0; t < 4; t++) {
            int idx = tid + 256 * t;
            int kk = idx >> 5, q = (idx & 31) * 4;
            *(float4*)&sW[kk * 128 + q]   = *(const float4*)&W2[(k0 + kk) * FEAT + q];
            *(float4*)&bufB[kk * 128 + q] = *(const float4*)&g_h1T[(k0 + kk) * BB + m0 + q];
        }
        __syncthreads();
#pragma unroll 8
        for (int kk = 0; kk < 32; kk++)
            gstep(acc, &sW[kk * 128 + t8], &bufB[kk * 128 + x8]);
        __syncthreads();
    }
#pragma unroll
    for (int i = 0; i < 8; i++) {
        float bv = b2[t8 + i];
        float v[8];
#pragma unroll
        for (int j = 0; j < 4; j++) {
            float2 p = unpk(acc[i][j]);
            v[2 * j]     = fmaxf(p.x + bv, 0.f);
            v[2 * j + 1] = fmaxf(p.y + bv, 0.f);
        }
        *(float4*)&bufA[(t8 + i) * 128 + x8]     = make_float4(v[0], v[1], v[2], v[3]);
        *(float4*)&bufA[(t8 + i) * 128 + x8 + 4] = make_float4(v[4], v[5], v[6], v[7]);
    }
    __syncthreads();

    float* cur = bufA;
    float* nxt = bufB;
    for (int l = 0; l < DEPTH; l++) {
        const float* w = cW + l * 16384;
#pragma unroll
        for (int t = 0; t < 16; t++) {
            int idx = (tid + 256 * t) * 4;
            *(float4*)&sW[idx] = *(const float4*)&w[idx];
        }
        __syncthreads();
        zacc(acc);
        {
            const float* pa = sW + t8;
            const float* pb = cur + x8;
#pragma unroll 8
            for (int d = 0; d < FEAT; d++) {
                gstep(acc, pa, pb);
                pa += 128; pb += 128;
            }
        }
#pragma unroll
        for (int i = 0; i < 8; i++) {
            float bv = cB[l * FEAT + t8 + i];
            float v[8];
#pragma unroll
            for (int j = 0; j < 4; j++) {
                float2 p = unpk(acc[i][j]);
                v[2 * j]     = fmaxf(p.x + bv, 0.f);
                v[2 * j + 1] = fmaxf(p.y + bv, 0.f);
            }
            *(float4*)&nxt[(t8 + i) * 128 + x8]     = make_float4(v[0], v[1], v[2], v[3]);
            *(float4*)&nxt[(t8 + i) * 128 + x8 + 4] = make_float4(v[4], v[5], v[6], v[7]);
        }
        __syncthreads();
        float* tmp = cur; cur = nxt; nxt = tmp;
    }

    const float IWF = 0.42f * 1.8f / 256.f;
    const float AWF = 0.3f / 128.f;

    for (int k = 0; k < NCOND; k++) {
        {
            const float* w = g_M + k * 16384;
#pragma unroll
            for (int t = 0; t < 16; t++) {
                int idx = (tid + 256 * t) * 4;
                *(float4*)&sW[idx] = *(const float4*)&w[idx];
            }
        }
        __syncthreads();

        zacc(acc);
        {
            const float* pa = sW + t8;
            const float* pb = cur + x8;
#pragma unroll 8
            for (int d = 0; d < FEAT; d++) {
                gstep(acc, pa, pb);
                pa += 128; pb += 128;
            }
        }
        {
            float s[8];
#pragma unroll
            for (int j = 0; j < 8; j++) s[j] = 0.f;
#pragma unroll
            for (int i = 0; i < 8; i++) {
                float4 v0 = *(const float4*)&cur[(t8 + i) * 128 + x8];
                float4 v1 = *(const float4*)&cur[(t8 + i) * 128 + x8 + 4];
                float2 p;
                p = unpk(acc[i][0]); s[0] += p.x * v0.x; s[1] += p.y * v0.y;
                p = unpk(acc[i][1]); s[2] += p.x * v0.z; s[3] += p.y * v0.w;
                p = unpk(acc[i][2]); s[4] += p.x * v1.x; s[5] += p.y * v1.y;
                p = unpk(acc[i][3]); s[6] += p.x * v1.z; s[7] += p.y * v1.w;
            }
#pragma unroll
            for (int j = 0; j < 8; j++) atomicAdd(&iw_s[x8 + j], s[j]);
        }
        __syncthreads();

        {
            const float* w = rW + k * 16384;
#pragma unroll
            for (int t = 0; t < 16; t++) {
                int idx = (tid + 256 * t) * 4;
                *(float4*)&sW[idx] = *(const float4*)&w[idx];
            }
        }
        __syncthreads();

        zacc(acc);
        {
            const float* pa = cur + t8;
            const float* pb = sW + x8;
#pragma unroll 8
            for (int d = 0; d < FEAT; d++) {
                gstep(acc, pa, pb);
                pa += 128; pb += 128;
            }
        }

        float4 rb0 = *(const float4*)&rB[k * FEAT + x8];
        float4 rb1 = *(const float4*)&rB[k * FEAT + x8 + 4];
        float rbv[8] = {rb0.x, rb0.y, rb0.z, rb0.w, rb1.x, rb1.y, rb1.z, rb1.w};
#pragma unroll
        for (int i = 0; i < 8; i++) {
            int r = t8 + i;
            float wgt = iw_s[r] * IWF + aw_s[r] * AWF;
            float v[8];
#pragma unroll
            for (int j = 0; j < 4; j++) {
                float2 p = unpk(acc[i][j]);
                v[2 * j]     = (p.x + rbv[2 * j]) * wgt;
                v[2 * j + 1] = (p.y + rbv[2 * j + 1]) * wgt;
            }
            float* op = out + ((m0 + r) * NCOND + k) * FEAT + x8;
            *(float4*)&op[0] = make_float4(v[0], v[1], v[2], v[3]);
            *(float4*)&op[4] = make_float4(v[4], v[5], v[6], v[7]);
        }
        __syncthreads();
        if (tid < 128) iw_s[tid] = 0.f;
    }
}

// ---------------------------------------------------------------------------
extern "C" void kernel_launch(void* const* d_in, const int* in_sizes, int n_in,
                              void* d_out, int out_size)
{
    (void)in_sizes; (void)n_in; (void)out_size;
    const float* sup  = (const float*)d_in[0];
    const float* anom = (const float*)d_in[1];
    const float* ind  = (const float*)d_in[2];
    const float* W1   = (const float*)d_in[3];
    const float* b1   = (const float*)d_in[4];
    const float* W2   = (const float*)d_in[5];
    const float* b2   = (const float*)d_in[6];
    const float* cW   = (const float*)d_in[7];
    const float* cB   = (const float*)d_in[8];
    const float* refp = (const float*)d_in[9];
    const float* objp = (const float*)d_in[10];
    const float* rW   = (const float*)d_in[11];
    const float* rB   = (const float*)d_in[12];
    float* out = (float*)d_out;

    cudaFuncSetAttribute(k_gemm1_mma, cudaFuncAttributeMaxDynamicSharedMemorySize,
                         SMEM_G1B);
    cudaFuncSetAttribute(k_fused, cudaFuncAttributeMaxDynamicSharedMemorySize,
                         SMEM_C_BYTES);

    k_prepB<<<dim3(100, 8), 256>>>(W1);
    k_gemm1_mma<<<128, 256, SMEM_G1B>>>(sup, anom, ind, b1);
    k_prep<<<dim3(NCOND, 4), 256>>>(refp, objp);
    k_fused<<<128, 256, SMEM_C_BYTES>>>(anom, W2, b2, cW, cB, rW, rB, out);
}

// round 17
// speedup vs baseline: 2.2902x; 1.5082x over previous
#include <cuda_runtime.h>
#include <cuda_bf16.h>
#include <cstdint>

// Problem constants
#define BB    16384
#define DSUP  1024
#define DANOM 128
#define DIND  2048
#define DIN   3200
#define H1D   256
#define FEAT  128
#define DEPTH 12
#define NCOND 14
#define CAP   256

typedef unsigned long long u64;

// Scratch (all bf16 split pairs)
__device__ __nv_bfloat16 g_h1hi[BB * H1D];     // h1 hi  [m][256]
__device__ __nv_bfloat16 g_h1lo[BB * H1D];     // h1 lo
__device__ __nv_bfloat16 g_Bhi[H1D * DIN];     // W1^T hi [256][3200] (for gemm1)
__device__ __nv_bfloat16 g_Blo[H1D * DIN];
__device__ __nv_bfloat16 g_W2t_hi[FEAT * H1D]; // W2^T [e=128][k=256]
__device__ __nv_bfloat16 g_W2t_lo[FEAT * H1D];
__device__ __nv_bfloat16 g_cWt_hi[DEPTH * FEAT * FEAT];  // cons^T [l][e][d]
__device__ __nv_bfloat16 g_cWt_lo[DEPTH * FEAT * FEAT];
__device__ __nv_bfloat16 g_rWt_hi[NCOND * FEAT * FEAT];  // ret^T [k][e][d]
__device__ __nv_bfloat16 g_rWt_lo[NCOND * FEAT * FEAT];
__device__ __nv_bfloat16 g_Mt_hi[NCOND * FEAT * FEAT];   // M^T  [k][e][d]
__device__ __nv_bfloat16 g_Mt_lo[NCOND * FEAT * FEAT];

__device__ __forceinline__ uint32_t smem_u32(const void* p) {
    uint32_t a;
    asm("{ .reg .u64 t; cvta.to.shared.u64 t, %1; cvt.u32.u64 %0, t; }"
        : "=r"(a) : "l"(p));
    return a;
}

#define LDMX4(r0, r1, r2, r3, addr) \
    asm volatile("ldmatrix.sync.aligned.m8n8.x4.shared.b16 {%0,%1,%2,%3}, [%4];" \
        : "=r"(r0), "=r"(r1), "=r"(r2), "=r"(r3) : "r"(addr))
#define LDMX2(r0, r1, addr) \
    asm volatile("ldmatrix.sync.aligned.m8n8.x2.shared.b16 {%0,%1}, [%2];" \
        : "=r"(r0), "=r"(r1) : "r"(addr))
#define MMA16816(d, a, b0_, b1_) \
    asm volatile("mma.sync.aligned.m16n8k16.row.col.f32.bf16.bf16.f32 " \
        "{%0,%1,%2,%3}, {%4,%5,%6,%7}, {%8,%9}, {%0,%1,%2,%3};" \
        : "+f"((d)[0]), "+f"((d)[1]), "+f"((d)[2]), "+f"((d)[3]) \
        : "r"((a)[0]), "r"((a)[1]), "r"((a)[2]), "r"((a)[3]), \
          "r"(b0_), "r"(b1_))

__device__ __forceinline__ uint32_t pack_hi2(float a, float b) {
    return (uint32_t)__bfloat16_as_ushort(__float2bfloat16(a)) |
           ((uint32_t)__bfloat16_as_ushort(__float2bfloat16(b)) << 16);
}
__device__ __forceinline__ uint32_t pack_lo2(float a, float b) {
    float ah = __bfloat162float(__float2bfloat16(a));
    float bh = __bfloat162float(__float2bfloat16(b));
    return (uint32_t)__bfloat16_as_ushort(__float2bfloat16(a - ah)) |
           ((uint32_t)__bfloat16_as_ushort(__float2bfloat16(b - bh)) << 16);
}

// ---------------------------------------------------------------------------
// k_prepB: transpose + split W1 [3200][256] -> g_Bhi/g_Blo [256][3200]
// ---------------------------------------------------------------------------
__global__ __launch_bounds__(256)
void k_prepB(const float* __restrict__ W1)
{
    __shared__ float t[32][33];
    const int k0 = blockIdx.x * 32;
    const int n0 = blockIdx.y * 32;
    const int tx = threadIdx.x & 31, ty = threadIdx.x >> 5;
#pragma unroll
    for (int i = 0; i < 32; i += 8)
        t[ty + i][tx] = W1[(k0 + ty + i) * H1D + n0 + tx];
    __syncthreads();
#pragma unroll
    for (int i = 0; i < 32; i += 8) {
        int n = n0 + ty + i, k = k0 + tx;
        float x = t[tx][ty + i];
        __nv_bfloat16 hi = __float2bfloat16(x);
        g_Bhi[n * DIN + k] = hi;
        g_Blo[n * DIN + k] = __float2bfloat16(x - __bfloat162float(hi));
    }
}

// ---------------------------------------------------------------------------
// k_prepW: transpose + split W2 / cons_W / ret_W.
// grid (8, 4, 27): z<12 cons, z<26 ret, z==26 W2 (K=256). src [k][128].
// ---------------------------------------------------------------------------
__global__ __launch_bounds__(256)
void k_prepW(const float* __restrict__ W2, const float* __restrict__ cW,
             const float* __restrict__ rW)
{
    __shared__ float t[32][33];
    const int z = blockIdx.z;
    const int K = (z == 26) ? 256 : 128;
    const int k0 = blockIdx.x * 32;
    if (k0 >= K) return;
    const int e0 = blockIdx.y * 32;
    const float* src;
    __nv_bfloat16 *dhi, *dlo;
    if (z < 12)      { src = cW + z * 16384;  dhi = g_cWt_hi + z * 16384;  dlo = g_cWt_lo + z * 16384; }
    else if (z < 26) { int b = z - 12; src = rW + b * 16384; dhi = g_rWt_hi + b * 16384; dlo = g_rWt_lo + b * 16384; }
    else             { src = W2; dhi = g_W2t_hi; dlo = g_W2t_lo; }
    const int tx = threadIdx.x & 31, ty = threadIdx.x >> 5;
#pragma unroll
    for (int i = 0; i < 32; i += 8)
        t[ty + i][tx] = src[(k0 + ty + i) * FEAT + e0 + tx];
    __syncthreads();
#pragma unroll
    for (int i = 0; i < 32; i += 8) {
        int e = e0 + ty + i, k = k0 + tx;
        float x = t[tx][ty + i];
        __nv_bfloat16 hi = __float2bfloat16(x);
        dhi[e * K + k] = hi;
        dlo[e * K + k] = __float2bfloat16(x - __bfloat162float(hi));
    }
}

// ---------------------------------------------------------------------------
// k_gemm1_mma: h1 = relu(X @ W1 + b1) via split-bf16 mma.sync (unchanged core,
// epilogue now writes g_h1hi/g_h1lo [m][256] bf16).
// ---------------------------------------------------------------------------
#define KCH 64
#define NCH (DIN / KCH)
#define A_HI 0
#define A_LO 18432
#define B_HI 36864
#define B_LO (36864 + 36864)
#define BUFB 110592
#define SMEM_G1B (2 * BUFB)

__device__ __forceinline__ void g1_loadA(float4* areg, int c, int m0, int tid,
    const float* __restrict__ sup, const float* __restrict__ anom,
    const float* __restrict__ ind)
{
    const int kg = c * KCH;
    const float* P; int W, koff;
    if (kg < DSUP)              { P = sup;  W = DSUP;  koff = kg; }
    else if (kg < DSUP + DANOM) { P = anom; W = DANOM; koff = kg - DSUP; }
    else                        { P = ind;  W = DIND;  koff = kg - DSUP - DANOM; }
#pragma unroll
    for (int it = 0; it < 8; it++) {
        int idx = tid + 256 * it;
        int r = idx >> 4, q = idx & 15;
        areg[it] = *(const float4*)&P[(m0 + r) * W + koff + q * 4];
    }
}

__device__ __forceinline__ void g1_store(const float4* areg, int c, int tid, char* ab)
{
#pragma unroll
    for (int it = 0; it < 8; it++) {
        int idx = tid + 256 * it;
        int r = idx >> 4, q = idx & 15;
        float4 v = areg[it];
        uint2 hv = make_uint2(pack_hi2(v.x, v.y), pack_hi2(v.z, v.w));
        uint2 lv = make_uint2(pack_lo2(v.x, v.y), pack_lo2(v.z, v.w));
        *(uint2*)(ab + A_HI + r * 144 + q * 8) = hv;
        *(uint2*)(ab + A_LO + r * 144 + q * 8) = lv;
    }
    const int kg = c * KCH;
#pragma unroll
    for (int it = 0; it < 8; it++) {
        int idx = tid + 256 * it;
        int n = idx >> 3, u = idx & 7;
        *(uint4*)(ab + B_HI + n * 144 + u * 16) =
            *(const uint4*)&g_Bhi[n * DIN + kg + u * 8];
    }
#pragma unroll
    for (int it = 0; it < 8; it++) {
        int idx = tid + 256 * it;
        int n = idx >> 3, u = idx & 7;
        *(uint4*)(ab + B_LO + n * 144 + u * 16) =
            *(const uint4*)&g_Blo[n * DIN + kg + u * 8];
    }
}

__global__ __launch_bounds__(256)
void k_gemm1_mma(const float* __restrict__ sup, const float* __restrict__ anom,
                 const float* __restrict__ ind, const float* __restrict__ b1)
{
    extern __shared__ __align__(16) char smem[];
    const uint32_t sbase = smem_u32(smem);
    const int tid  = threadIdx.x;
    const int lane = tid & 31;
    const int wid  = tid >> 5;
    const int wm   = wid >> 2;
    const int wn   = wid & 3;
    const int m0   = blockIdx.x * 128;

    float acc[4][8][4];
#pragma unroll
    for (int i = 0; i < 4; i++)
#pragma unroll
        for (int j = 0; j < 8; j++)
#pragma unroll
            for (int r = 0; r < 4; r++) acc[i][j][r] = 0.f;

    float4 areg[8];
    g1_loadA(areg, 0, m0, tid, sup, anom, ind);
    g1_store(areg, 0, tid, smem);
    __syncthreads();

    for (int c = 0; c < NCH; c++) {
        const int b = c & 1;
        if (c + 1 < NCH)
            g1_loadA(areg, c + 1, m0, tid, sup, anom, ind);

        const uint32_t base = sbase + b * BUFB;
        const uint32_t arow0 = base + A_HI + (wm * 64 + (lane & 15)) * 144
                               + (lane >> 4) * 16;
        const uint32_t brow0 = base + B_HI + (wn * 64 + (lane & 7)) * 144
                               + ((lane >> 3) & 1) * 16;
#pragma unroll
        for (int ks = 0; ks < 4; ks++) {
            uint32_t ah[4][4], al[4][4];
#pragma unroll
            for (int i = 0; i < 4; i++) {
                uint32_t aa = arow0 + i * (16 * 144) + ks * 32;
                LDMX4(ah[i][0], ah[i][1], ah[i][2], ah[i][3], aa);
                LDMX4(al[i][0], al[i][1], al[i][2], al[i][3], aa + (A_LO - A_HI));
            }
#pragma unroll
            for (int j = 0; j < 8; j++) {
                uint32_t bh0, bh1, bl0, bl1;
                uint32_t ba = brow0 + j * (8 * 144) + ks * 32;
                LDMX2(bh0, bh1, ba);
                LDMX2(bl0, bl1, ba + (B_LO - B_HI));
#pragma unroll
                for (int i = 0; i < 4; i++) {
                    MMA16816(acc[i][j], ah[i], bh0, bh1);
                    MMA16816(acc[i][j], ah[i], bl0, bl1);
                    MMA16816(acc[i][j], al[i], bh0, bh1);
                }
            }
        }
        if (c + 1 < NCH)
            g1_store(areg, c + 1, tid, smem + ((c + 1) & 1) * BUFB);
        __syncthreads();
    }

    // epilogue: bias + relu, split to bf16 hi/lo, store [m][256]
    const int q    = lane & 3;
    const int rrow = lane >> 2;
    uint32_t* h1hi = (uint32_t*)g_h1hi;
    uint32_t* h1lo = (uint32_t*)g_h1lo;
#pragma unroll
    for (int i = 0; i < 4; i++) {
        int m = m0 + wm * 64 + i * 16 + rrow;
#pragma unroll
        for (int j = 0; j < 8; j++) {
            int nb = wn * 64 + j * 8 + 2 * q;
            float b0v = b1[nb], b1v = b1[nb + 1];
            float v0 = fmaxf(acc[i][j][0] + b0v, 0.f);
            float v1 = fmaxf(acc[i][j][1] + b1v, 0.f);
            float v2 = fmaxf(acc[i][j][2] + b0v, 0.f);
            float v3 = fmaxf(acc[i][j][3] + b1v, 0.f);
            h1hi[m * 128 + nb / 2]       = pack_hi2(v0, v1);
            h1lo[m * 128 + nb / 2]       = pack_lo2(v0, v1);
            h1hi[(m + 8) * 128 + nb / 2] = pack_hi2(v2, v3);
            h1lo[(m + 8) * 128 + nb / 2] = pack_lo2(v2, v3);
        }
    }
}

// ---------------------------------------------------------------------------
// k_prep: M_k^T[e][d] = sum_c ref[k][c][d]*obj[k][c][e], stored split bf16.
// ---------------------------------------------------------------------------
__global__ __launch_bounds__(256, 2)
void k_prep(const float* __restrict__ refp, const float* __restrict__ objp)
{
    __shared__ __align__(16) float refS[64 * 128];
    __shared__ __align__(16) float objS[64 * 32];
    const int k   = blockIdx.x;
    const int e0  = blockIdx.y * 32;
    const int tid = threadIdx.x;
    const int d0  = (tid >> 3) * 4;
    const int el  = (tid & 7) * 4;

    float acc[4][4];
#pragma unroll
    for (int u = 0; u < 4; u++)
#pragma unroll
        for (int v = 0; v < 4; v++) acc[u][v] = 0.f;

    for (int c0 = 0; c0 < CAP; c0 += 64) {
#pragma unroll
        for (int t = 0; t < 8; t++) {
            int idx = tid + 256 * t;
            int cc = idx >> 5, qq = idx & 31;
            *(float4*)&refS[cc * 128 + qq * 4] =
                *(const float4*)&refp[k * CAP * FEAT + (c0 + cc) * FEAT + qq * 4];
        }
#pragma unroll
        for (int t = 0; t < 2; t++) {
            int idx = tid + 256 * t;
            int cc = idx >> 3, qq = idx & 7;
            *(float4*)&objS[cc * 32 + qq * 4] =
                *(const float4*)&objp[k * CAP * FEAT + (c0 + cc) * FEAT + e0 + qq * 4];
        }
        __syncthreads();
#pragma unroll 8
        for (int cc = 0; cc < 64; cc++) {
            float4 rv = *(const float4*)&refS[cc * 128 + d0];
            float4 ov = *(const float4*)&objS[cc * 32 + el];
            float r[4] = {rv.x, rv.y, rv.z, rv.w};
            float o[4] = {ov.x, ov.y, ov.z, ov.w};
#pragma unroll
            for (int u = 0; u < 4; u++)
#pragma unroll
                for (int v = 0; v < 4; v++) acc[u][v] += r[u] * o[v];
        }
        __syncthreads();
    }
    // transposed split store: [e][d], 4 consecutive d per v
#pragma unroll
    for (int v = 0; v < 4; v++) {
        int e = e0 + el + v;
        uint2 hv = make_uint2(pack_hi2(acc[0][v], acc[1][v]),
                              pack_hi2(acc[2][v], acc[3][v]));
        uint2 lv = make_uint2(pack_lo2(acc[0][v], acc[1][v]),
                              pack_lo2(acc[2][v], acc[3][v]));
        *(uint2*)&g_Mt_hi[k * 16384 + e * 128 + d0] = hv;
        *(uint2*)&g_Mt_lo[k * 16384 + e * 128 + d0] = lv;
    }
}

// ---------------------------------------------------------------------------
// k_fused_mma: per-tile chain via split-bf16 mma.sync.
// smem: S(hi+lo, 272B pitch, 2x34816) | Wbuf0(2x34816) | Wbuf1 | aw,iw
// ---------------------------------------------------------------------------
#define PIT 272
#define HALF 34816               // 128 * 272
#define S_OFF 0
#define W0_OFF 69632
#define W1_OFF 139264
#define AW_OFF 208896
#define SMEM_F (208896 + 1024)

__device__ __forceinline__ const __nv_bfloat16* wsrc_hi(int g) {
    if (g < 12) return g_cWt_hi + g * 16384;
    int t = (g - 12) >> 1;
    return ((g - 12) & 1) ? g_rWt_hi + t * 16384 : g_Mt_hi + t * 16384;
}
__device__ __forceinline__ const __nv_bfloat16* wsrc_lo(int g) {
    if (g < 12) return g_cWt_lo + g * 16384;
    int t = (g - 12) >> 1;
    return ((g - 12) & 1) ? g_rWt_lo + t * 16384 : g_Mt_lo + t * 16384;
}

__device__ __forceinline__ void f_stageW(char* dst, const __nv_bfloat16* hi,
                                         const __nv_bfloat16* lo, int tid)
{
#pragma unroll
    for (int t = 0; t < 8; t++) {
        int idx = tid + 256 * t;
        int r = idx >> 4, u = idx & 15;
        *(uint4*)(dst + r * PIT + u * 16)        = *(const uint4*)(hi + r * 128 + u * 8);
        *(uint4*)(dst + HALF + r * PIT + u * 16) = *(const uint4*)(lo + r * 128 + u * 8);
    }
}

// stage A for GEMM2 from g_h1hi/lo [m][256], chunk kc
__device__ __forceinline__ void f_stageA2(char* dst, int m0, int kc, int tid)
{
    const char* hsrc = (const char*)g_h1hi;
    const char* lsrc = (const char*)g_h1lo;
#pragma unroll
    for (int t = 0; t < 8; t++) {
        int idx = tid + 256 * t;
        int r = idx >> 4, u = idx & 15;
        long so = (long)(m0 + r) * 512 + kc * 256 + u * 16;
        *(uint4*)(dst + r * PIT + u * 16)        = *(const uint4*)(hsrc + so);
        *(uint4*)(dst + HALF + r * PIT + u * 16) = *(const uint4*)(lsrc + so);
    }
}

// stage W2t chunk kc from g_W2t [e][256]
__device__ __forceinline__ void f_stageW2(char* dst, int kc, int tid)
{
    const char* hsrc = (const char*)g_W2t_hi;
    const char* lsrc = (const char*)g_W2t_lo;
#pragma unroll
    for (int t = 0; t < 8; t++) {
        int idx = tid + 256 * t;
        int r = idx >> 4, u = idx & 15;
        long so = (long)r * 512 + kc * 256 + u * 16;
        *(uint4*)(dst + r * PIT + u * 16)        = *(const uint4*)(hsrc + so);
        *(uint4*)(dst + HALF + r * PIT + u * 16) = *(const uint4*)(lsrc + so);
    }
}

// one K=128 split-bf16 GEMM: acc += S[128x128] @ Wt^T
__device__ __forceinline__ void f_mma(uint32_t sS, uint32_t sW,
                                      float acc[4][4][4], int lane, int wm, int wn)
{
    const uint32_t arow0 = sS + (wm * 64 + (lane & 15)) * PIT + (lane >> 4) * 16;
    const uint32_t brow0 = sW + (wn * 32 + (lane & 7)) * PIT + ((lane >> 3) & 1) * 16;
#pragma unroll
    for (int ks = 0; ks < 8; ks++) {
        uint32_t ah[4][4], al[4][4];
#pragma unroll
        for (int i = 0; i < 4; i++) {
            uint32_t aa = arow0 + i * (16 * PIT) + ks * 32;
            LDMX4(ah[i][0], ah[i][1], ah[i][2], ah[i][3], aa);
            LDMX4(al[i][0], al[i][1], al[i][2], al[i][3], aa + HALF);
        }
#pragma unroll
        for (int j = 0; j < 4; j++) {
            uint32_t bh0, bh1, bl0, bl1;
            uint32_t ba = brow0 + j * (8 * PIT) + ks * 32;
            LDMX2(bh0, bh1, ba);
            LDMX2(bl0, bl1, ba + HALF);
#pragma unroll
            for (int i = 0; i < 4; i++) {
                MMA16816(acc[i][j], ah[i], bh0, bh1);
                MMA16816(acc[i][j], ah[i], bl0, bl1);
                MMA16816(acc[i][j], al[i], bh0, bh1);
            }
        }
    }
}

// relu(acc + bias) -> S (split hi/lo)
__device__ __forceinline__ void f_epi_relu(char* S, float acc[4][4][4],
                                           const float* __restrict__ bias,
                                           int lane, int wm, int wn)
{
    const int rrow = lane >> 2, q = lane & 3;
#pragma unroll
    for (int i = 0; i < 4; i++) {
        int r0 = wm * 64 + i * 16 + rrow;
#pragma unroll
        for (int j = 0; j < 4; j++) {
            int e = wn * 32 + j * 8 + 2 * q;
            float2 bv = *(const float2*)&bias[e];
            float v0 = fmaxf(acc[i][j][0] + bv.x, 0.f);
            float v1 = fmaxf(acc[i][j][1] + bv.y, 0.f);
            float v2 = fmaxf(acc[i][j][2] + bv.x, 0.f);
            float v3 = fmaxf(acc[i][j][3] + bv.y, 0.f);
            *(uint32_t*)(S + r0 * PIT + e * 2)              = pack_hi2(v0, v1);
            *(uint32_t*)(S + HALF + r0 * PIT + e * 2)       = pack_lo2(v0, v1);
            *(uint32_t*)(S + (r0 + 8) * PIT + e * 2)        = pack_hi2(v2, v3);
            *(uint32_t*)(S + HALF + (r0 + 8) * PIT + e * 2) = pack_lo2(v2, v3);
        }
    }
}

// iw[r] += sum_e P[r][e] * S[r][e]  (shuffle-reduced atomics)
__device__ __forceinline__ void f_iw(const char* S, float acc[4][4][4],
                                     float* iw_s, int lane, int wm, int wn)
{
    const int rrow = lane >> 2, q = lane & 3;
#pragma unroll
    for (int i = 0; i < 4; i++) {
        int r0 = wm * 64 + i * 16 + rrow;
        float p0 = 0.f, p1 = 0.f;
#pragma unroll
        for (int j = 0; j < 4; j++) {
            int e = wn * 32 + j * 8 + 2 * q;
            uint32_t h0 = *(const uint32_t*)(S + r0 * PIT + e * 2);
            uint32_t l0 = *(const uint32_t*)(S + HALF + r0 * PIT + e * 2);
            uint32_t h1 = *(const uint32_t*)(S + (r0 + 8) * PIT + e * 2);
            uint32_t l1 = *(const uint32_t*)(S + HALF + (r0 + 8) * PIT + e * 2);
            float s0a = __bfloat162float(__ushort_as_bfloat16((unsigned short)h0))
                      + __bfloat162float(__ushort_as_bfloat16((unsigned short)l0));
            float s0b = __bfloat162float(__ushort_as_bfloat16((unsigned short)(h0 >> 16)))
                      + __bfloat162float(__ushort_as_bfloat16((unsigned short)(l0 >> 16)));
            float s1a = __bfloat162float(__ushort_as_bfloat16((unsigned short)h1))
                      + __bfloat162float(__ushort_as_bfloat16((unsigned short)l1));
            float s1b = __bfloat162float(__ushort_as_bfloat16((unsigned short)(h1 >> 16)))
                      + __bfloat162float(__ushort_as_bfloat16((unsigned short)(l1 >> 16)));
            p0 += acc[i][j][0] * s0a + acc[i][j][1] * s0b;
            p1 += acc[i][j][2] * s1a + acc[i][j][3] * s1b;
        }
        p0 += __shfl_xor_sync(0xFFFFFFFF, p0, 1);
        p0 += __shfl_xor_sync(0xFFFFFFFF, p0, 2);
        p1 += __shfl_xor_sync(0xFFFFFFFF, p1, 1);
        p1 += __shfl_xor_sync(0xFFFFFFFF, p1, 2);
        if (q == 0) {
            atomicAdd(&iw_s[r0], p0);
            atomicAdd(&iw_s[r0 + 8], p1);
        }
    }
}

// out[(m0+r)*14 + kb][e] = (acc + rb) * wgt
__device__ __forceinline__ void f_epi_out(float* __restrict__ out,
                                          float acc[4][4][4],
                                          const float* __restrict__ rBk,
                                          const float* iw_s, const float* aw_s,
                                          int m0, int kb, int lane, int wm, int wn)
{
    const float IWF = 0.42f * 1.8f / 256.f;
    const float AWF = 0.3f / 128.f;
    const int rrow = lane >> 2, q = lane & 3;
#pragma unroll
    for (int i = 0; i < 4; i++) {
        int r0 = wm * 64 + i * 16 + rrow;
        float w0 = iw_s[r0] * IWF + aw_s[r0] * AWF;
        float w1 = iw_s[r0 + 8] * IWF + aw_s[r0 + 8] * AWF;
        float* o0 = out + ((long)(m0 + r0) * NCOND + kb) * FEAT;
        float* o1 = out + ((long)(m0 + r0 + 8) * NCOND + kb) * FEAT;
#pragma unroll
        for (int j = 0; j < 4; j++) {
            int e = wn * 32 + j * 8 + 2 * q;
            float2 rb = *(const float2*)&rBk[e];
            *(float2*)&o0[e] = make_float2((acc[i][j][0] + rb.x) * w0,
                                           (acc[i][j][1] + rb.y) * w0);
            *(float2*)&o1[e] = make_float2((acc[i][j][2] + rb.x) * w1,
                                           (acc[i][j][3] + rb.y) * w1);
        }
    }
}

__global__ __launch_bounds__(256)
void k_fused_mma(const float* __restrict__ anom,
                 const float* __restrict__ b2, const float* __restrict__ cB,
                 const float* __restrict__ rB, float* __restrict__ out)
{
    extern __shared__ __align__(16) char sm[];
    char* Sb  = sm + S_OFF;
    char* Wb0 = sm + W0_OFF;
    char* Wb1 = sm + W1_OFF;
    float* aw_s = (float*)(sm + AW_OFF);
    float* iw_s = aw_s + 128;
    const uint32_t sbase = smem_u32(sm);
    const uint32_t sS = sbase + S_OFF;

    const int tid  = threadIdx.x;
    const int lane = tid & 31;
    const int wid  = tid >> 5;
    const int wm   = wid >> 2;
    const int wn   = wid & 3;
    const int m0   = blockIdx.x * 128;

    if (tid < 128) { aw_s[tid] = 0.f; iw_s[tid] = 0.f; }
    __syncthreads();

    // anomaly weights
    {
        const float4* ap = (const float4*)(anom + (long)m0 * DANOM);
#pragma unroll
        for (int t = 0; t < 16; t++) {
            int idx = tid + 256 * t;
            float4 v = ap[idx];
            atomicAdd(&aw_s[idx >> 5],
                      fabsf(v.x) + fabsf(v.y) + fabsf(v.z) + fabsf(v.w));
        }
    }

    float acc[4][4][4];
#pragma unroll
    for (int i = 0; i < 4; i++)
#pragma unroll
        for (int j = 0; j < 4; j++)
#pragma unroll
            for (int r = 0; r < 4; r++) acc[i][j][r] = 0.f;

    // ---- GEMM2 (K=256, two chunks, accumulated) ----
    f_stageA2(Sb, m0, 0, tid);
    f_stageW2(Wb0, 0, tid);
    __syncthreads();
    f_mma(sS, sbase + W0_OFF, acc, lane, wm, wn);
    __syncthreads();
    f_stageA2(Sb, m0, 1, tid);
    f_stageW2(Wb1, 1, tid);
    f_stageW(Wb0, wsrc_hi(0), wsrc_lo(0), tid);   // cons0 -> buf0
    __syncthreads();
    f_mma(sS, sbase + W1_OFF, acc, lane, wm, wn);
    __syncthreads();
    f_epi_relu(Sb, acc, b2, lane, wm, wn);

    // ---- 40 GEMMs: 12 layers + 14 x (M, R) ----
    for (int g = 0; g < 40; g++) {
        __syncthreads();
        char* wb_nxt = (g & 1) ? Wb0 : Wb1;
        uint32_t wcur = (g & 1) ? (sbase + W1_OFF) : (sbase + W0_OFF);
        if (g + 1 < 40) f_stageW(wb_nxt, wsrc_hi(g + 1), wsrc_lo(g + 1), tid);
        bool isM = (g >= 12) && (((g - 12) & 1) == 0);
        if (isM) {
            if (tid < 128) iw_s[tid] = 0.f;
            __syncthreads();
        }
#pragma unroll
        for (int i = 0; i < 4; i++)
#pragma unroll
            for (int j = 0; j < 4; j++)
#pragma unroll
                for (int r = 0; r < 4; r++) acc[i][j][r] = 0.f;
        f_mma(sS, wcur, acc, lane, wm, wn);
        if (g < 12) {
            __syncthreads();
            f_epi_relu(Sb, acc, cB + g * FEAT, lane, wm, wn);
        } else if (isM) {
            f_iw(Sb, acc, iw_s, lane, wm, wn);
        } else {
            int t = (g - 13) >> 1;
            f_epi_out(out, acc, rB + t * FEAT, iw_s, aw_s, m0, t, lane, wm, wn);
        }
    }
}

// ---------------------------------------------------------------------------
extern "C" void kernel_launch(void* const* d_in, const int* in_sizes, int n_in,
                              void* d_out, int out_size)
{
    (void)in_sizes; (void)n_in; (void)out_size;
    const float* sup  = (const float*)d_in[0];
    const float* anom = (const float*)d_in[1];
    const float* ind  = (const float*)d_in[2];
    const float* W1   = (const float*)d_in[3];
    const float* b1   = (const float*)d_in[4];
    const float* W2   = (const float*)d_in[5];
    const float* b2   = (const float*)d_in[6];
    const float* cW   = (const float*)d_in[7];
    const float* cB   = (const float*)d_in[8];
    const float* refp = (const float*)d_in[9];
    const float* objp = (const float*)d_in[10];
    const float* rW   = (const float*)d_in[11];
    const float* rB   = (const float*)d_in[12];
    float* out = (float*)d_out;

    cudaFuncSetAttribute(k_gemm1_mma, cudaFuncAttributeMaxDynamicSharedMemorySize,
                         SMEM_G1B);
    cudaFuncSetAttribute(k_fused_mma, cudaFuncAttributeMaxDynamicSharedMemorySize,
                         SMEM_F);

    k_prepB<<<dim3(100, 8), 256>>>(W1);
    k_prepW<<<dim3(8, 4, 27), 256>>>(W2, cW, rW);
    k_gemm1_mma<<<128, 256, SMEM_G1B>>>(sup, anom, ind, b1);
    k_prep<<<dim3(NCOND, 4), 256>>>(refp, objp);
    k_fused_mma<<<128, 256, SMEM_F>>>(anom, b2, cB, rB, out);
}